// round 1
// baseline (speedup 1.0000x reference)
#include <cuda_runtime.h>
#include <math.h>

#define NN 50000
#define NE 800000
#define INF 128
#define HID 256
#define NCLS 64

// ---------------- device scratch (no allocation allowed) ----------------
__device__ int   g_deg[NN];
__device__ int   g_cursor[NN];
__device__ int   g_off[NN + 1];
__device__ int   g_csr[NE];
__device__ float g_invdeg[NN];
__device__ int   g_tsum[64];
__device__ float g_h0[(size_t)NN * HID];
__device__ float g_h1[(size_t)NN * HID];
__device__ float g_agg[(size_t)NN * HID];   // reused: agg0(128) / agg1(256) / t(64)+aggt(64)
__device__ float g_W2sf[HID * NCLS];
__device__ float g_W2nf[HID * NCLS];
__device__ float g_bf[NCLS];

// ---------------- CSR build ----------------
__global__ void k_zero_counts() {
    int i = blockIdx.x * blockDim.x + threadIdx.x;
    if (i < NN) { g_deg[i] = 0; g_cursor[i] = 0; }
}

__global__ void k_count(const int* __restrict__ dst) {
    int e = blockIdx.x * blockDim.x + threadIdx.x;
    if (e < NE) atomicAdd(&g_deg[dst[e]], 1);
}

// tile-wise exclusive scan (tile = 1024)
__global__ void k_scan_tiles() {
    __shared__ int sh[1024];
    int t = threadIdx.x;
    int i = blockIdx.x * 1024 + t;
    int v = (i < NN) ? g_deg[i] : 0;
    sh[t] = v;
    __syncthreads();
    for (int d = 1; d < 1024; d <<= 1) {
        int x = 0;
        if (t >= d) x = sh[t - d];
        __syncthreads();
        sh[t] += x;
        __syncthreads();
    }
    if (i < NN) g_off[i] = sh[t] - v;          // exclusive
    if (t == 1023) g_tsum[blockIdx.x] = sh[t]; // inclusive tile sum
}

__global__ void k_scan_sums(int ntiles) {
    __shared__ int sh[64];
    int t = threadIdx.x;
    int v = (t < ntiles) ? g_tsum[t] : 0;
    sh[t] = v;
    __syncthreads();
    for (int d = 1; d < 64; d <<= 1) {
        int x = 0;
        if (t >= d) x = sh[t - d];
        __syncthreads();
        sh[t] += x;
        __syncthreads();
    }
    if (t < ntiles) g_tsum[t] = sh[t] - v;     // exclusive over tile sums
}

__global__ void k_scan_fix() {
    int i = blockIdx.x * blockDim.x + threadIdx.x;
    if (i < NN) {
        g_off[i] += g_tsum[i >> 10];
        g_invdeg[i] = 1.0f / fmaxf((float)g_deg[i], 1.0f);
    }
    if (i == 0) g_off[NN] = NE;
}

__global__ void k_fill(const int* __restrict__ src, const int* __restrict__ dst) {
    int e = blockIdx.x * blockDim.x + threadIdx.x;
    if (e < NE) {
        int d = dst[e];
        int pos = g_off[d] + atomicAdd(&g_cursor[d], 1);
        g_csr[pos] = src[e];
    }
}

// ---------------- fold fc into layer 2 ----------------
// g_W2sf = W2s @ Wfc, g_W2nf = W2n @ Wfc, g_bf = b2 @ Wfc + bfc
__global__ void k_fuse_weights(const float* __restrict__ W2s, const float* __restrict__ W2n,
                               const float* __restrict__ b2,  const float* __restrict__ Wfc,
                               const float* __restrict__ bfc) {
    int j = blockIdx.x * blockDim.x + threadIdx.x;
    if (j < HID * NCLS) {
        int r = j / NCLS, c = j % NCLS;
        float s = 0.f, n = 0.f;
        #pragma unroll 8
        for (int k = 0; k < HID; ++k) {
            float w = Wfc[k * NCLS + c];
            s += W2s[r * HID + k] * w;
            n += W2n[r * HID + k] * w;
        }
        g_W2sf[j] = s;
        g_W2nf[j] = n;
    }
    if (j < NCLS) {
        float b = bfc[j];
        for (int k = 0; k < HID; ++k) b += b2[k] * Wfc[k * NCLS + j];
        g_bf[j] = b;
    }
}

// ---------------- mean-neighbor gather (no atomics, L2-resident rows) ----------------
template <int D>
__global__ void k_gather_mean(const float* __restrict__ h, float* __restrict__ agg) {
    constexpr int TPN = D / 4;  // one float4 per thread
    int gtid = blockIdx.x * blockDim.x + threadIdx.x;
    int node = gtid / TPN;
    int c    = gtid % TPN;
    if (node >= NN) return;
    int s = g_off[node], e = g_off[node + 1];
    float4 acc = make_float4(0.f, 0.f, 0.f, 0.f);
    const float4* hp = (const float4*)h;
    for (int idx = s; idx < e; ++idx) {
        int src = g_csr[idx];
        float4 v = hp[(size_t)src * TPN + c];
        acc.x += v.x; acc.y += v.y; acc.z += v.z; acc.w += v.w;
    }
    float w = g_invdeg[node];
    ((float4*)agg)[(size_t)node * TPN + c] =
        make_float4(acc.x * w, acc.y * w, acc.z * w, acc.w * w);
}

// ---------------- fused dual-input GEMM ----------------
// C[M x Nc] = A0[M x K0] @ B0[K0 x Nc] (+ A1 @ B1) (+ bias row) (+ addend matrix)
__global__ __launch_bounds__(256)
void k_gemm(const float* __restrict__ A0, const float* __restrict__ B0, int K0,
            const float* __restrict__ A1, const float* __restrict__ B1, int K1,
            const float* __restrict__ bias, const float* __restrict__ addend,
            float* __restrict__ C, int M, int Nc) {
    constexpr int BM = 64, BN = 64, BK = 16;
    __shared__ float As[BK][BM];
    __shared__ float Bs[BK][BN];

    int tid = threadIdx.x;
    int tx = tid & 15, ty = tid >> 4;
    int bm = blockIdx.y * BM, bn = blockIdx.x * BN;

    int a_r = tid >> 2;          // 0..63
    int a_c = (tid & 3) * 4;     // 0,4,8,12
    int b_r = tid >> 4;          // 0..15
    int b_c = (tid & 15) * 4;    // 0..60

    float acc[4][4] = {};

    #pragma unroll
    for (int pair = 0; pair < 2; ++pair) {
        const float* A = pair ? A1 : A0;
        const float* B = pair ? B1 : B0;
        int K = pair ? K1 : K0;
        if (A == nullptr) continue;
        for (int k0 = 0; k0 < K; k0 += BK) {
            float4 av = make_float4(0.f, 0.f, 0.f, 0.f);
            int row = bm + a_r;
            if (row < M) av = *(const float4*)(A + (size_t)row * K + k0 + a_c);
            As[a_c + 0][a_r] = av.x;
            As[a_c + 1][a_r] = av.y;
            As[a_c + 2][a_r] = av.z;
            As[a_c + 3][a_r] = av.w;
            float4 bv = *(const float4*)(B + (size_t)(k0 + b_r) * Nc + bn + b_c);
            *(float4*)&Bs[b_r][b_c] = bv;
            __syncthreads();
            #pragma unroll
            for (int k = 0; k < BK; ++k) {
                float4 a = *(const float4*)&As[k][ty * 4];
                float4 b = *(const float4*)&Bs[k][tx * 4];
                acc[0][0] += a.x * b.x; acc[0][1] += a.x * b.y; acc[0][2] += a.x * b.z; acc[0][3] += a.x * b.w;
                acc[1][0] += a.y * b.x; acc[1][1] += a.y * b.y; acc[1][2] += a.y * b.z; acc[1][3] += a.y * b.w;
                acc[2][0] += a.z * b.x; acc[2][1] += a.z * b.y; acc[2][2] += a.z * b.z; acc[2][3] += a.z * b.w;
                acc[3][0] += a.w * b.x; acc[3][1] += a.w * b.y; acc[3][2] += a.w * b.z; acc[3][3] += a.w * b.w;
            }
            __syncthreads();
        }
    }

    #pragma unroll
    for (int i = 0; i < 4; ++i) {
        int row = bm + ty * 4 + i;
        if (row >= M) continue;
        int col = bn + tx * 4;
        float4 c = make_float4(acc[i][0], acc[i][1], acc[i][2], acc[i][3]);
        if (bias) {
            c.x += bias[col + 0]; c.y += bias[col + 1];
            c.z += bias[col + 2]; c.w += bias[col + 3];
        }
        if (addend) {
            float4 d = *(const float4*)(addend + (size_t)row * Nc + col);
            c.x += d.x; c.y += d.y; c.z += d.z; c.w += d.w;
        }
        *(float4*)(C + (size_t)row * Nc + col) = c;
    }
}

// ---------------- launch ----------------
extern "C" void kernel_launch(void* const* d_in, const int* in_sizes, int n_in,
                              void* d_out, int out_size) {
    const float* x    = (const float*)d_in[0];
    const int*   esrc = (const int*)d_in[1];
    const int*   edst = (const int*)d_in[2];
    const float* W0s  = (const float*)d_in[3];
    const float* W0n  = (const float*)d_in[4];
    const float* b0   = (const float*)d_in[5];
    const float* W1s  = (const float*)d_in[6];
    const float* W1n  = (const float*)d_in[7];
    const float* b1   = (const float*)d_in[8];
    const float* W2s  = (const float*)d_in[9];
    const float* W2n  = (const float*)d_in[10];
    const float* b2   = (const float*)d_in[11];
    const float* Wfc  = (const float*)d_in[12];
    const float* bfc  = (const float*)d_in[13];
    float* out = (float*)d_out;

    float *h0, *h1, *agg, *w2sf, *w2nf, *bf;
    cudaGetSymbolAddress((void**)&h0,   g_h0);
    cudaGetSymbolAddress((void**)&h1,   g_h1);
    cudaGetSymbolAddress((void**)&agg,  g_agg);
    cudaGetSymbolAddress((void**)&w2sf, g_W2sf);
    cudaGetSymbolAddress((void**)&w2nf, g_W2nf);
    cudaGetSymbolAddress((void**)&bf,   g_bf);

    const int TB = 256;
    int nblk_n = (NN + TB - 1) / TB;
    int nblk_e = (NE + TB - 1) / TB;
    int ntiles = (NN + 1023) / 1024;

    // CSR build
    k_zero_counts<<<nblk_n, TB>>>();
    k_count<<<nblk_e, TB>>>(edst);
    k_scan_tiles<<<ntiles, 1024>>>();
    k_scan_sums<<<1, 64>>>(ntiles);
    k_scan_fix<<<nblk_n, TB>>>();
    k_fill<<<nblk_e, TB>>>(esrc, edst);

    // fold fc into layer 2
    k_fuse_weights<<<(HID * NCLS + TB - 1) / TB, TB>>>(W2s, W2n, b2, Wfc, bfc);

    dim3 g256((HID) / 64, (NN + 63) / 64);   // Nc=256
    dim3 g64((NCLS) / 64, (NN + 63) / 64);   // Nc=64

    // layer 0: agg at 128-dim, then h0 = x@W0s + agg0@W0n + b0
    k_gather_mean<INF><<<(NN * (INF / 4) + TB - 1) / TB, TB>>>(x, agg);
    k_gemm<<<g256, TB>>>(x, W0s, INF, agg, W0n, INF, b0, nullptr, h0, NN, HID);

    // layer 1: agg at 256-dim, h1 = h0@W1s + agg1@W1n + b1
    k_gather_mean<HID><<<(NN * (HID / 4) + TB - 1) / TB, TB>>>(h0, agg);
    k_gemm<<<g256, TB>>>(h0, W1s, HID, agg, W1n, HID, b1, nullptr, h1, NN, HID);

    // layer 2 + fc folded: t = h1@W2nf (64-dim), aggt = mean(t),
    // out = h1@W2sf + aggt + bf
    float* t    = agg;
    float* aggt = agg + (size_t)NN * NCLS;
    k_gemm<<<g64, TB>>>(h1, w2nf, HID, nullptr, nullptr, 0, nullptr, nullptr, t, NN, NCLS);
    k_gather_mean<NCLS><<<(NN * (NCLS / 4) + TB - 1) / TB, TB>>>(t, aggt);
    k_gemm<<<g64, TB>>>(h1, w2sf, HID, nullptr, nullptr, 0, bf, aggt, out, NN, NCLS);
}